// round 5
// baseline (speedup 1.0000x reference)
#include <cuda_runtime.h>
#include <cuda_bf16.h>
#include <math.h>
#include <stdint.h>

#define Bb 4
#define Ss 1024
#define Dd 1024
#define Hh 16
#define HD 64
#define BHt (Bb*Hh)
#define Mrows (Bb*Ss)

// ---------------- device scratch ----------------
__device__ __nv_bfloat16 g_qh[(size_t)Mrows*Dd];
__device__ __nv_bfloat16 g_ql[(size_t)Mrows*Dd];
__device__ __nv_bfloat16 g_kh[(size_t)Mrows*Dd];
__device__ __nv_bfloat16 g_kl[(size_t)Mrows*Dd];
__device__ __nv_bfloat16 g_vh[(size_t)Mrows*Dd];
__device__ __nv_bfloat16 g_vl[(size_t)Mrows*Dd];
__device__ float g_x[(size_t)Mrows*Dd];
__device__ float g_rowsum[(size_t)BHt*Ss];
__device__ __nv_bfloat16 g_ph[(size_t)BHt*Ss*Ss];
__device__ __nv_bfloat16 g_pl[(size_t)BHt*Ss*Ss];
__device__ float g_p_fallback[(size_t)BHt*Ss*Ss];

// ---------------- helpers ----------------
__device__ __forceinline__ uint32_t smem_u32(const void* p) {
    uint32_t a;
    asm("{ .reg .u64 t; cvta.to.shared.u64 t, %1; cvt.u32.u64 %0, t; }" : "=r"(a) : "l"(p));
    return a;
}
__device__ __forceinline__ void ldsm_x4(uint32_t* r, uint32_t addr) {
    asm volatile("ldmatrix.sync.aligned.m8n8.x4.shared.b16 {%0,%1,%2,%3}, [%4];"
                 : "=r"(r[0]), "=r"(r[1]), "=r"(r[2]), "=r"(r[3]) : "r"(addr));
}
__device__ __forceinline__ void ldsm_x2t(uint32_t* r, uint32_t addr) {
    asm volatile("ldmatrix.sync.aligned.m8n8.x2.trans.shared.b16 {%0,%1}, [%2];"
                 : "=r"(r[0]), "=r"(r[1]) : "r"(addr));
}
__device__ __forceinline__ void mma16816(float* c, const uint32_t* a, const uint32_t* b) {
    asm volatile(
        "mma.sync.aligned.m16n8k16.row.col.f32.bf16.bf16.f32 "
        "{%0,%1,%2,%3}, {%4,%5,%6,%7}, {%8,%9}, {%0,%1,%2,%3};"
        : "+f"(c[0]), "+f"(c[1]), "+f"(c[2]), "+f"(c[3])
        : "r"(a[0]), "r"(a[1]), "r"(a[2]), "r"(a[3]), "r"(b[0]), "r"(b[1]));
}
__device__ __forceinline__ void split2(float x, float y, uint32_t& h, uint32_t& l) {
    __nv_bfloat16 hx = __float2bfloat16_rn(x);
    __nv_bfloat16 hy = __float2bfloat16_rn(y);
    __nv_bfloat162 hp; hp.x = hx; hp.y = hy;
    __nv_bfloat162 lp;
    lp.x = __float2bfloat16_rn(x - __bfloat162float(hx));
    lp.y = __float2bfloat16_rn(y - __bfloat162float(hy));
    h = *(uint32_t*)&hp;
    l = *(uint32_t*)&lp;
}
__device__ __forceinline__ void split8(const float4 a, const float4 b, uint4& h, uint4& l) {
    split2(a.x, a.y, h.x, l.x);
    split2(a.z, a.w, h.y, l.y);
    split2(b.x, b.y, h.z, l.z);
    split2(b.z, b.w, h.w, l.w);
}
__device__ __forceinline__ float2 bf2f2(uint32_t u) {
    __nv_bfloat162 t = *(__nv_bfloat162*)&u;
    return make_float2(__bfloat162float(t.x), __bfloat162float(t.y));
}

// --------- 128x128 GEMM: fp32 in, in-kernel hi/lo split, 3-term MMA ---------
__global__ __launch_bounds__(256) void gemm_f32_tc(
    const float* __restrict__ A, const float* __restrict__ W,
    const float* __restrict__ bias,
    float* __restrict__ Cf, __nv_bfloat16* __restrict__ Ch,
    __nv_bfloat16* __restrict__ Cl, int mode,
    int Mn, int Nn, int Kn)
{
    __shared__ __align__(16) __nv_bfloat16 As[128][64];
    __shared__ __align__(16) __nv_bfloat16 Bs[2][32][128];

    const int tid = threadIdx.x;
    const int warp = tid >> 5, lane = tid & 31;
    const int wm = (warp >> 2) << 6;
    const int wn = (warp & 3) << 5;
    const int bm = blockIdx.y << 7, bn = blockIdx.x << 7;

    const uint32_t as0 = smem_u32(&As[0][0]);
    const uint32_t bs0 = smem_u32(&Bs[0][0][0]);

    float acc[4][4][4];
#pragma unroll
    for (int i = 0; i < 4; i++)
#pragma unroll
        for (int j = 0; j < 4; j++)
#pragma unroll
            for (int r = 0; r < 4; r++) acc[i][j][r] = 0.f;

    const int arow = tid >> 1, acol = (tid & 1) << 4;
    const float* gA = A + (size_t)(bm + arow) * Kn + acol;
    const int bk = tid >> 3, bcol = (tid & 7) << 4;
    const float* gW = W + (size_t)bk * Nn + bn + bcol;

    char* apB = (char*)(&As[0][0]) + arow * 128;
    char* bpB = (char*)(&Bs[0][0][0]) + bk * 256;
    const int swa = arow & 7, swb = bk & 7;
    const int ac0 = (tid & 1) << 1;
    const int bc0 = (tid & 7) << 1;

    // prefetch k0 = 0
    float4 ra[4], rw[4];
#pragma unroll
    for (int i = 0; i < 4; i++) {
        ra[i] = *(const float4*)(gA + (i << 2));
        rw[i] = *(const float4*)(gW + (i << 2));
    }

    for (int k0 = 0; k0 < Kn; k0 += 32) {
        uint4 ah0, al0, ah1, al1, wh0, wl0, wh1, wl1;
        split8(ra[0], ra[1], ah0, al0);
        split8(ra[2], ra[3], ah1, al1);
        split8(rw[0], rw[1], wh0, wl0);
        split8(rw[2], rw[3], wh1, wl1);
        __syncthreads();
        *(uint4*)(apB + (((ac0 | 0) ^ swa) << 4)) = ah0;
        *(uint4*)(apB + (((ac0 | 1) ^ swa) << 4)) = ah1;
        *(uint4*)(apB + ((((ac0 | 0) + 4) ^ swa) << 4)) = al0;
        *(uint4*)(apB + ((((ac0 | 1) + 4) ^ swa) << 4)) = al1;
        *(uint4*)(bpB + (((bc0 | 0) ^ swb) << 4)) = wh0;
        *(uint4*)(bpB + (((bc0 | 1) ^ swb) << 4)) = wh1;
        *(uint4*)(bpB + 8192 + (((bc0 | 0) ^ swb) << 4)) = wl0;
        *(uint4*)(bpB + 8192 + (((bc0 | 1) ^ swb) << 4)) = wl1;
        __syncthreads();

        if (k0 + 32 < Kn) {
#pragma unroll
            for (int i = 0; i < 4; i++) {
                ra[i] = *(const float4*)(gA + k0 + 32 + (i << 2));
                rw[i] = *(const float4*)(gW + (size_t)(k0 + 32) * Nn + (i << 2));
            }
        }

#pragma unroll
        for (int ks = 0; ks < 2; ks++) {
            uint32_t af[2][4][4];
            uint32_t bf[2][4][2];
            const int r15 = lane & 15;
            const int choff = (ks << 1) + (lane >> 4);
#pragma unroll
            for (int mf = 0; mf < 4; mf++) {
                int row = wm + (mf << 4) + r15;
                uint32_t base = as0 + row * 128;
                int sw = row & 7;
                ldsm_x4(af[0][mf], base + ((choff ^ sw) << 4));
                ldsm_x4(af[1][mf], base + (((choff + 4) ^ sw) << 4));
            }
            const int krow = (ks << 4) + r15;
            const int swk = krow & 7;
#pragma unroll
            for (int nf = 0; nf < 4; nf++) {
                int chunk = (wn + (nf << 3)) >> 3;
                uint32_t ad = bs0 + krow * 256 + ((chunk ^ swk) << 4);
                ldsm_x2t(bf[0][nf], ad);
                ldsm_x2t(bf[1][nf], ad + 8192);
            }
#pragma unroll
            for (int mf = 0; mf < 4; mf++)
#pragma unroll
                for (int nf = 0; nf < 4; nf++) {
                    mma16816(acc[mf][nf], af[0][mf], bf[0][nf]);
                    mma16816(acc[mf][nf], af[0][mf], bf[1][nf]);
                    mma16816(acc[mf][nf], af[1][mf], bf[0][nf]);
                }
        }
    }

    const int gr = lane >> 2, gc = (lane & 3) << 1;
#pragma unroll
    for (int mf = 0; mf < 4; mf++) {
        int r0 = bm + wm + (mf << 4) + gr;
#pragma unroll
        for (int nf = 0; nf < 4; nf++) {
            int col = bn + wn + (nf << 3) + gc;
            float2 bv = *(const float2*)(bias + col);
            float c00 = acc[mf][nf][0] + bv.x, c01 = acc[mf][nf][1] + bv.y;
            float c10 = acc[mf][nf][2] + bv.x, c11 = acc[mf][nf][3] + bv.y;
            if (mode == 0) {
                *(float2*)(Cf + (size_t)r0 * Nn + col) = make_float2(c00, c01);
                *(float2*)(Cf + (size_t)(r0 + 8) * Nn + col) = make_float2(c10, c11);
            } else {
                uint32_t h, l;
                split2(c00, c01, h, l);
                *(uint32_t*)(Ch + (size_t)r0 * Nn + col) = h;
                *(uint32_t*)(Cl + (size_t)r0 * Nn + col) = l;
                split2(c10, c11, h, l);
                *(uint32_t*)(Ch + (size_t)(r0 + 8) * Nn + col) = h;
                *(uint32_t*)(Cl + (size_t)(r0 + 8) * Nn + col) = l;
            }
        }
    }
}

// ---- energy: S = QK^T/8, P_unnorm = exp(S)*mask as bf16 hi/lo; rowsums ----
__global__ __launch_bounds__(256) void attn_energy2(
    const __nv_bfloat16* __restrict__ qh, const __nv_bfloat16* __restrict__ ql,
    const __nv_bfloat16* __restrict__ kh, const __nv_bfloat16* __restrict__ kl,
    const int* __restrict__ mask,
    __nv_bfloat16* __restrict__ Ph, __nv_bfloat16* __restrict__ Pl)
{
    __shared__ __align__(16) __nv_bfloat16 Kh[64][64], Kl[64][64];
    __shared__ int msk[1024];
    __shared__ float red[64][4];

    const int tid = threadIdx.x;
    const int warp = tid >> 5, lane = tid & 31;
    const int wm = (warp >> 2) << 5;
    const int wn = (warp & 3) << 4;
    const int bh = blockIdx.y;
    const int b = bh >> 4, h = bh & 15;
    const int q0 = blockIdx.x << 6;

    const uint32_t kh0 = smem_u32(&Kh[0][0]);
    const uint32_t kl0 = smem_u32(&Kl[0][0]);
    const int gr = lane >> 2, gc = (lane & 3) << 1;
    const int r15 = lane & 15;

#pragma unroll
    for (int i = 0; i < 4; i++)
        msk[tid + (i << 8)] = mask[b * Ss + tid + (i << 8)];

    const int row = tid >> 2;
    const int c0 = (tid & 3) << 1;
    const int swc0 = (((c0 | 0) ^ (row & 7)) << 4) + row * 128;
    const int swc1 = (((c0 | 1) ^ (row & 7)) << 4) + row * 128;

    // stage Q in the K region, hoist fragments to registers
    {
        const size_t base = ((size_t)(b * Ss + q0 + row)) * Dd + h * HD;
        *(uint4*)((char*)Kh + swc0) = *(const uint4*)(qh + base + ((c0 | 0) << 3));
        *(uint4*)((char*)Kh + swc1) = *(const uint4*)(qh + base + ((c0 | 1) << 3));
        *(uint4*)((char*)Kl + swc0) = *(const uint4*)(ql + base + ((c0 | 0) << 3));
        *(uint4*)((char*)Kl + swc1) = *(const uint4*)(ql + base + ((c0 | 1) << 3));
    }
    __syncthreads();

    uint32_t qHf[4][2][4], qLf[4][2][4];
#pragma unroll
    for (int ks = 0; ks < 4; ks++) {
        const int choff = (ks << 1) + (lane >> 4);
#pragma unroll
        for (int mf = 0; mf < 2; mf++) {
            int qr = wm + (mf << 4) + r15;
            int off = qr * 128 + ((choff ^ (qr & 7)) << 4);
            ldsm_x4(qHf[ks][mf], kh0 + off);
            ldsm_x4(qLf[ks][mf], kl0 + off);
        }
    }

    // prefetch K tile 0
    uint4 rkh[2], rkl[2];
    {
        const size_t base = ((size_t)(b * Ss + row)) * Dd + h * HD;
        rkh[0] = *(const uint4*)(kh + base + ((c0 | 0) << 3));
        rkh[1] = *(const uint4*)(kh + base + ((c0 | 1) << 3));
        rkl[0] = *(const uint4*)(kl + base + ((c0 | 0) << 3));
        rkl[1] = *(const uint4*)(kl + base + ((c0 | 1) << 3));
    }

    float rs[2][2] = {{0.f, 0.f}, {0.f, 0.f}};
    const float sc = 0.125f;

    for (int kt = 0; kt < 16; kt++) {
        const int k0 = kt << 6;
        __syncthreads();
        *(uint4*)((char*)Kh + swc0) = rkh[0];
        *(uint4*)((char*)Kh + swc1) = rkh[1];
        *(uint4*)((char*)Kl + swc0) = rkl[0];
        *(uint4*)((char*)Kl + swc1) = rkl[1];
        __syncthreads();

        if (kt < 15) {
            const size_t base = ((size_t)(b * Ss + k0 + 64 + row)) * Dd + h * HD;
            rkh[0] = *(const uint4*)(kh + base + ((c0 | 0) << 3));
            rkh[1] = *(const uint4*)(kh + base + ((c0 | 1) << 3));
            rkl[0] = *(const uint4*)(kl + base + ((c0 | 0) << 3));
            rkl[1] = *(const uint4*)(kl + base + ((c0 | 1) << 3));
        }

        float eacc[2][2][4];
#pragma unroll
        for (int i = 0; i < 2; i++)
#pragma unroll
            for (int j = 0; j < 2; j++)
#pragma unroll
                for (int r = 0; r < 4; r++) eacc[i][j][r] = 0.f;

#pragma unroll
        for (int ks = 0; ks < 4; ks++) {
            int nrow = wn + ((lane >> 4) << 3) + (lane & 7);
            int kch = (ks << 1) + ((lane >> 3) & 1);
            int boff = nrow * 128 + ((kch ^ (nrow & 7)) << 4);
            uint32_t bH[4], bL[4];
            ldsm_x4(bH, kh0 + boff);
            ldsm_x4(bL, kl0 + boff);
#pragma unroll
            for (int mf = 0; mf < 2; mf++)
#pragma unroll
                for (int nf = 0; nf < 2; nf++) {
                    mma16816(eacc[mf][nf], qHf[ks][mf], bH + nf * 2);
                    mma16816(eacc[mf][nf], qHf[ks][mf], bL + nf * 2);
                    mma16816(eacc[mf][nf], qLf[ks][mf], bH + nf * 2);
                }
        }

        // epilogue: exp + mask -> bf16 hi/lo, rowsums
#pragma unroll
        for (int mf = 0; mf < 2; mf++) {
            int row0 = q0 + wm + (mf << 4) + gr;
#pragma unroll
            for (int nf = 0; nf < 2; nf++) {
                int col = k0 + wn + (nf << 3) + gc;
                int m0 = msk[col], m1 = msk[col + 1];
                float e0 = m0 ? __expf(eacc[mf][nf][0] * sc) : 0.f;
                float e1 = m1 ? __expf(eacc[mf][nf][1] * sc) : 0.f;
                float e2 = m0 ? __expf(eacc[mf][nf][2] * sc) : 0.f;
                float e3 = m1 ? __expf(eacc[mf][nf][3] * sc) : 0.f;
                rs[mf][0] += e0 + e1;
                rs[mf][1] += e2 + e3;
                uint32_t hp, lp;
                split2(e0, e1, hp, lp);
                *(uint32_t*)(Ph + ((size_t)bh * Ss + row0) * Ss + col) = hp;
                *(uint32_t*)(Pl + ((size_t)bh * Ss + row0) * Ss + col) = lp;
                split2(e2, e3, hp, lp);
                *(uint32_t*)(Ph + ((size_t)bh * Ss + row0 + 8) * Ss + col) = hp;
                *(uint32_t*)(Pl + ((size_t)bh * Ss + row0 + 8) * Ss + col) = lp;
            }
        }
    }

#pragma unroll
    for (int mf = 0; mf < 2; mf++)
#pragma unroll
        for (int hf = 0; hf < 2; hf++) {
            float v = rs[mf][hf];
            v += __shfl_xor_sync(0xffffffff, v, 1);
            v += __shfl_xor_sync(0xffffffff, v, 2);
            if ((lane & 3) == 0)
                red[wm + (mf << 4) + gr + (hf << 3)][warp & 3] = v;
        }
    __syncthreads();
    if (tid < 64)
        g_rowsum[(size_t)bh * Ss + q0 + tid] =
            red[tid][0] + red[tid][1] + red[tid][2] + red[tid][3];
}

// ---- PV: X = diag(inv) * P_unnorm @ V; writes normalized fp32 P ----
__global__ __launch_bounds__(256) void attn_pv2(
    const __nv_bfloat16* __restrict__ Phg, const __nv_bfloat16* __restrict__ Plg,
    const __nv_bfloat16* __restrict__ vh, const __nv_bfloat16* __restrict__ vl,
    float* __restrict__ P, float* __restrict__ X)
{
    __shared__ __align__(16) __nv_bfloat16 Phs[64][64], Pls[64][64];
    __shared__ __align__(16) __nv_bfloat16 Vhs[64][64], Vls[64][64];
    __shared__ float sinv[64];

    const int tid = threadIdx.x;
    const int warp = tid >> 5, lane = tid & 31;
    const int wm = (warp >> 2) << 5;
    const int wn = (warp & 3) << 4;
    const int bh = blockIdx.y;
    const int b = bh >> 4, h = bh & 15;
    const int q0 = blockIdx.x << 6;

    const uint32_t ph0 = smem_u32(&Phs[0][0]);
    const uint32_t pl0 = smem_u32(&Pls[0][0]);
    const uint32_t vh0 = smem_u32(&Vhs[0][0]);
    const uint32_t vl0 = smem_u32(&Vls[0][0]);
    const int gr = lane >> 2, gc = (lane & 3) << 1;
    const int r15 = lane & 15;

    if (tid < 64)
        sinv[tid] = 1.0f / g_rowsum[(size_t)bh * Ss + q0 + tid];

    const int row = tid >> 2;
    const int c0 = (tid & 3) << 1;
    const int swc0 = (((c0 | 0) ^ (row & 7)) << 4) + row * 128;
    const int swc1 = (((c0 | 1) ^ (row & 7)) << 4) + row * 128;

    uint4 rph[2], rpl[2], rvh[2], rvl[2];
    {
        const size_t pbase = ((size_t)bh * Ss + q0 + row) * Ss;
        const size_t vbase = ((size_t)(b * Ss + row)) * Dd + h * HD;
        rph[0] = *(const uint4*)(Phg + pbase + ((c0 | 0) << 3));
        rph[1] = *(const uint4*)(Phg + pbase + ((c0 | 1) << 3));
        rpl[0] = *(const uint4*)(Plg + pbase + ((c0 | 0) << 3));
        rpl[1] = *(const uint4*)(Plg + pbase + ((c0 | 1) << 3));
        rvh[0] = *(const uint4*)(vh + vbase + ((c0 | 0) << 3));
        rvh[1] = *(const uint4*)(vh + vbase + ((c0 | 1) << 3));
        rvl[0] = *(const uint4*)(vl + vbase + ((c0 | 0) << 3));
        rvl[1] = *(const uint4*)(vl + vbase + ((c0 | 1) << 3));
    }

    float xacc[2][2][4];
#pragma unroll
    for (int i = 0; i < 2; i++)
#pragma unroll
        for (int j = 0; j < 2; j++)
#pragma unroll
            for (int r = 0; r < 4; r++) xacc[i][j][r] = 0.f;

    for (int kt = 0; kt < 16; kt++) {
        const int k0 = kt << 6;
        __syncthreads();
        *(uint4*)((char*)Phs + swc0) = rph[0];
        *(uint4*)((char*)Phs + swc1) = rph[1];
        *(uint4*)((char*)Pls + swc0) = rpl[0];
        *(uint4*)((char*)Pls + swc1) = rpl[1];
        *(uint4*)((char*)Vhs + swc0) = rvh[0];
        *(uint4*)((char*)Vhs + swc1) = rvh[1];
        *(uint4*)((char*)Vls + swc0) = rvl[0];
        *(uint4*)((char*)Vls + swc1) = rvl[1];

        // normalized fp32 P write from the held registers
        {
            float inv = sinv[row];
            float* pout = P + ((size_t)bh * Ss + q0 + row) * Ss + k0;
#pragma unroll
            for (int i = 0; i < 2; i++) {
                float2 h0 = bf2f2(rph[i].x), l0 = bf2f2(rpl[i].x);
                float2 h1 = bf2f2(rph[i].y), l1 = bf2f2(rpl[i].y);
                float2 h2 = bf2f2(rph[i].z), l2 = bf2f2(rpl[i].z);
                float2 h3 = bf2f2(rph[i].w), l3 = bf2f2(rpl[i].w);
                float4 o0 = {(h0.x + l0.x) * inv, (h0.y + l0.y) * inv,
                             (h1.x + l1.x) * inv, (h1.y + l1.y) * inv};
                float4 o1 = {(h2.x + l2.x) * inv, (h2.y + l2.y) * inv,
                             (h3.x + l3.x) * inv, (h3.y + l3.y) * inv};
                *(float4*)(pout + ((c0 | i) << 3)) = o0;
                *(float4*)(pout + ((c0 | i) << 3) + 4) = o1;
            }
        }
        __syncthreads();

        if (kt < 15) {
            const size_t pbase = ((size_t)bh * Ss + q0 + row) * Ss + k0 + 64;
            const size_t vbase = ((size_t)(b * Ss + k0 + 64 + row)) * Dd + h * HD;
            rph[0] = *(const uint4*)(Phg + pbase + ((c0 | 0) << 3));
            rph[1] = *(const uint4*)(Phg + pbase + ((c0 | 1) << 3));
            rpl[0] = *(const uint4*)(Plg + pbase + ((c0 | 0) << 3));
            rpl[1] = *(const uint4*)(Plg + pbase + ((c0 | 1) << 3));
            rvh[0] = *(const uint4*)(vh + vbase + ((c0 | 0) << 3));
            rvh[1] = *(const uint4*)(vh + vbase + ((c0 | 1) << 3));
            rvl[0] = *(const uint4*)(vl + vbase + ((c0 | 0) << 3));
            rvl[1] = *(const uint4*)(vl + vbase + ((c0 | 1) << 3));
        }

#pragma unroll
        for (int ks = 0; ks < 4; ks++) {
            const int choff = (ks << 1) + (lane >> 4);
            uint32_t aH[2][4], aL[2][4];
#pragma unroll
            for (int mf = 0; mf < 2; mf++) {
                int qr = wm + (mf << 4) + r15;
                int off = qr * 128 + ((choff ^ (qr & 7)) << 4);
                ldsm_x4(aH[mf], ph0 + off);
                ldsm_x4(aL[mf], pl0 + off);
            }
            const int krow = (ks << 4) + r15;
            const int swk = krow & 7;
            uint32_t bH[2][2], bL[2][2];
#pragma unroll
            for (int nf = 0; nf < 2; nf++) {
                int chunk = (wn + (nf << 3)) >> 3;
                int boff = krow * 128 + ((chunk ^ swk) << 4);
                ldsm_x2t(bH[nf], vh0 + boff);
                ldsm_x2t(bL[nf], vl0 + boff);
            }
#pragma unroll
            for (int mf = 0; mf < 2; mf++)
#pragma unroll
                for (int nf = 0; nf < 2; nf++) {
                    mma16816(xacc[mf][nf], aH[mf], bH[nf]);
                    mma16816(xacc[mf][nf], aH[mf], bL[nf]);
                    mma16816(xacc[mf][nf], aL[mf], bH[nf]);
                }
        }
    }

    float iv[2][2];
#pragma unroll
    for (int mf = 0; mf < 2; mf++) {
        iv[mf][0] = sinv[wm + (mf << 4) + gr];
        iv[mf][1] = sinv[wm + (mf << 4) + gr + 8];
    }
#pragma unroll
    for (int mf = 0; mf < 2; mf++) {
        int row0 = q0 + wm + (mf << 4) + gr;
#pragma unroll
        for (int nf = 0; nf < 2; nf++) {
            int col = h * HD + wn + (nf << 3) + gc;
            *(float2*)(X + ((size_t)(b * Ss + row0)) * Dd + col) =
                make_float2(xacc[mf][nf][0] * iv[mf][0], xacc[mf][nf][1] * iv[mf][0]);
            *(float2*)(X + ((size_t)(b * Ss + row0 + 8)) * Dd + col) =
                make_float2(xacc[mf][nf][2] * iv[mf][1], xacc[mf][nf][3] * iv[mf][1]);
        }
    }
}

// ---------------- launch ----------------
extern "C" void kernel_launch(void* const* d_in, const int* in_sizes, int n_in,
                              void* d_out, int out_size)
{
    const float* query = (const float*)d_in[0];
    const float* key   = (const float*)d_in[1];
    const float* value = (const float*)d_in[2];
    const int*   mask  = (const int*)d_in[3];
    const float* Wq = (const float*)d_in[4];  const float* bq = (const float*)d_in[5];
    const float* Wk = (const float*)d_in[6];  const float* bk = (const float*)d_in[7];
    const float* Wv = (const float*)d_in[8];  const float* bv = (const float*)d_in[9];
    const float* Wo = (const float*)d_in[10]; const float* bo = (const float*)d_in[11];

    float* out = (float*)d_out;
    const size_t BSD = (size_t)Bb * Ss * Dd;
    const size_t ATT = (size_t)BHt * Ss * Ss;

    void *pqh, *pql, *pkh, *pkl, *pvh, *pvl, *px, *pph, *ppl;
    cudaGetSymbolAddress(&pqh, g_qh);
    cudaGetSymbolAddress(&pql, g_ql);
    cudaGetSymbolAddress(&pkh, g_kh);
    cudaGetSymbolAddress(&pkl, g_kl);
    cudaGetSymbolAddress(&pvh, g_vh);
    cudaGetSymbolAddress(&pvl, g_vl);
    cudaGetSymbolAddress(&px, g_x);
    cudaGetSymbolAddress(&pph, g_ph);
    cudaGetSymbolAddress(&ppl, g_pl);
    __nv_bfloat16* qh = (__nv_bfloat16*)pqh;
    __nv_bfloat16* ql = (__nv_bfloat16*)pql;
    __nv_bfloat16* kh = (__nv_bfloat16*)pkh;
    __nv_bfloat16* kl = (__nv_bfloat16*)pkl;
    __nv_bfloat16* vh = (__nv_bfloat16*)pvh;
    __nv_bfloat16* vl = (__nv_bfloat16*)pvl;
    __nv_bfloat16* ph = (__nv_bfloat16*)pph;
    __nv_bfloat16* pl = (__nv_bfloat16*)ppl;
    float* x = (float*)px;

    float* P;
    if ((size_t)out_size >= BSD + ATT) {
        P = out + BSD;
    } else {
        void* pp;
        cudaGetSymbolAddress(&pp, g_p_fallback);
        P = (float*)pp;
    }

    dim3 gemm_grid(Dd / 128, Mrows / 128);  // (8, 32)

    gemm_f32_tc<<<gemm_grid, 256>>>(query, Wq, bq, nullptr, qh, ql, 1, Mrows, Dd, Dd);
    gemm_f32_tc<<<gemm_grid, 256>>>(key,   Wk, bk, nullptr, kh, kl, 1, Mrows, Dd, Dd);
    gemm_f32_tc<<<gemm_grid, 256>>>(value, Wv, bv, nullptr, vh, vl, 1, Mrows, Dd, Dd);

    attn_energy2<<<dim3(Ss / 64, BHt), 256>>>(qh, ql, kh, kl, mask, ph, pl);
    attn_pv2<<<dim3(Ss / 64, BHt), 256>>>(ph, pl, vh, vl, P, x);

    gemm_f32_tc<<<gemm_grid, 256>>>(x, Wo, bo, out, nullptr, nullptr, 0, Mrows, Dd, Dd);
}

// round 8
// speedup vs baseline: 1.1326x; 1.1326x over previous
#include <cuda_runtime.h>
#include <cuda_bf16.h>
#include <math.h>
#include <stdint.h>

#define Bb 4
#define Ss 1024
#define Dd 1024
#define Hh 16
#define HD 64
#define BHt (Bb*Hh)
#define Mrows (Bb*Ss)

// ---------------- device scratch ----------------
__device__ __nv_bfloat16 g_qh[(size_t)Mrows*Dd];
__device__ __nv_bfloat16 g_ql[(size_t)Mrows*Dd];
__device__ __nv_bfloat16 g_kh[(size_t)Mrows*Dd];
__device__ __nv_bfloat16 g_kl[(size_t)Mrows*Dd];
__device__ __nv_bfloat16 g_vh[(size_t)Mrows*Dd];
__device__ __nv_bfloat16 g_vl[(size_t)Mrows*Dd];
__device__ float g_x[(size_t)Mrows*Dd];
__device__ float g_rowsum[(size_t)BHt*Ss];
__device__ float g_p_fallback[(size_t)BHt*Ss*Ss];

// ---------------- helpers ----------------
__device__ __forceinline__ uint32_t smem_u32(const void* p) {
    uint32_t a;
    asm("{ .reg .u64 t; cvta.to.shared.u64 t, %1; cvt.u32.u64 %0, t; }" : "=r"(a) : "l"(p));
    return a;
}
__device__ __forceinline__ void ldsm_x4(uint32_t* r, uint32_t addr) {
    asm volatile("ldmatrix.sync.aligned.m8n8.x4.shared.b16 {%0,%1,%2,%3}, [%4];"
                 : "=r"(r[0]), "=r"(r[1]), "=r"(r[2]), "=r"(r[3]) : "r"(addr));
}
__device__ __forceinline__ void ldsm_x2t(uint32_t* r, uint32_t addr) {
    asm volatile("ldmatrix.sync.aligned.m8n8.x2.trans.shared.b16 {%0,%1}, [%2];"
                 : "=r"(r[0]), "=r"(r[1]) : "r"(addr));
}
__device__ __forceinline__ void mma16816(float* c, const uint32_t* a, const uint32_t* b) {
    asm volatile(
        "mma.sync.aligned.m16n8k16.row.col.f32.bf16.bf16.f32 "
        "{%0,%1,%2,%3}, {%4,%5,%6,%7}, {%8,%9}, {%0,%1,%2,%3};"
        : "+f"(c[0]), "+f"(c[1]), "+f"(c[2]), "+f"(c[3])
        : "r"(a[0]), "r"(a[1]), "r"(a[2]), "r"(a[3]), "r"(b[0]), "r"(b[1]));
}
__device__ __forceinline__ void split2(float x, float y, uint32_t& h, uint32_t& l) {
    __nv_bfloat16 hx = __float2bfloat16_rn(x);
    __nv_bfloat16 hy = __float2bfloat16_rn(y);
    __nv_bfloat162 hp; hp.x = hx; hp.y = hy;
    __nv_bfloat162 lp;
    lp.x = __float2bfloat16_rn(x - __bfloat162float(hx));
    lp.y = __float2bfloat16_rn(y - __bfloat162float(hy));
    h = *(uint32_t*)&hp;
    l = *(uint32_t*)&lp;
}
__device__ __forceinline__ void split8(const float4 a, const float4 b, uint4& h, uint4& l) {
    split2(a.x, a.y, h.x, l.x);
    split2(a.z, a.w, h.y, l.y);
    split2(b.x, b.y, h.z, l.z);
    split2(b.z, b.w, h.w, l.w);
}

// --------- 128x128 GEMM, double-buffered smem, 3-term hi/lo MMA ---------
// dynamic smem: stage s at s*32768: As 16384 bytes, Bs 16384 bytes.
#define G_STAGE 32768
#define G_BOFF  16384
#define G_SMEM  65536

__global__ __launch_bounds__(256) void gemm_f32_tc(
    const float* __restrict__ A, const float* __restrict__ W,
    const float* __restrict__ bias,
    float* __restrict__ Cf, __nv_bfloat16* __restrict__ Ch,
    __nv_bfloat16* __restrict__ Cl, int mode,
    int Mn, int Nn, int Kn)
{
    extern __shared__ __align__(16) char gsm[];

    const int tid = threadIdx.x;
    const int warp = tid >> 5, lane = tid & 31;
    const int wm = (warp >> 2) << 6;
    const int wn = (warp & 3) << 5;
    const int bm = blockIdx.y << 7, bn = blockIdx.x << 7;
    const uint32_t smb = smem_u32(gsm);
    const int KT = Kn >> 5;   // number of 32-wide k tiles (=32 for Kn=1024)

    float acc[4][4][4];
#pragma unroll
    for (int i = 0; i < 4; i++)
#pragma unroll
        for (int j = 0; j < 4; j++)
#pragma unroll
            for (int r = 0; r < 4; r++) acc[i][j][r] = 0.f;

    const int arow = tid >> 1;
    const float* gA = A + (size_t)(bm + arow) * Kn + ((tid & 1) << 4);
    const int bk = tid >> 3;
    const float* gW = W + (size_t)bk * Nn + bn + ((tid & 7) << 4);

    const int swa = arow & 7, swb = bk & 7;
    const int ac0 = (tid & 1) << 1;
    const int bc0 = (tid & 7) << 1;
    const uint32_t aoff0 = arow * 128 + (((ac0 | 0) ^ swa) << 4);
    const uint32_t aoff1 = arow * 128 + (((ac0 | 1) ^ swa) << 4);
    const uint32_t aoff2 = arow * 128 + ((((ac0 | 0) + 4) ^ swa) << 4);
    const uint32_t aoff3 = arow * 128 + ((((ac0 | 1) + 4) ^ swa) << 4);
    const uint32_t boff0 = bk * 256 + (((bc0 | 0) ^ swb) << 4);
    const uint32_t boff1 = bk * 256 + (((bc0 | 1) ^ swb) << 4);

    // prologue: tile 0 -> regs -> stage 0
    float4 ra[4], rw[4];
#pragma unroll
    for (int i = 0; i < 4; i++) {
        ra[i] = *(const float4*)(gA + (i << 2));
        rw[i] = *(const float4*)(gW + (i << 2));
    }
    {
        uint4 ah0, al0, ah1, al1, wh0, wl0, wh1, wl1;
        split8(ra[0], ra[1], ah0, al0);
        split8(ra[2], ra[3], ah1, al1);
        split8(rw[0], rw[1], wh0, wl0);
        split8(rw[2], rw[3], wh1, wl1);
        char* st = gsm;
        *(uint4*)(st + aoff0) = ah0;
        *(uint4*)(st + aoff1) = ah1;
        *(uint4*)(st + aoff2) = al0;
        *(uint4*)(st + aoff3) = al1;
        *(uint4*)(st + G_BOFF + boff0) = wh0;
        *(uint4*)(st + G_BOFF + boff1) = wh1;
        *(uint4*)(st + G_BOFF + 8192 + boff0) = wl0;
        *(uint4*)(st + G_BOFF + 8192 + boff1) = wl1;
    }
    __syncthreads();

    const int r15 = lane & 15;
    for (int t = 0; t < KT; t++) {
        const int cur = t & 1;
        const uint32_t as0 = smb + cur * G_STAGE;
        const uint32_t bs0 = as0 + G_BOFF;

        // issue next tile's global loads (latency hidden behind MMA)
        if (t + 1 < KT) {
            const int ko = (t + 1) << 5;
#pragma unroll
            for (int i = 0; i < 4; i++) {
                ra[i] = *(const float4*)(gA + ko + (i << 2));
                rw[i] = *(const float4*)(gW + (size_t)ko * Nn + (i << 2));
            }
        }

        // MMA on current stage
#pragma unroll
        for (int ks = 0; ks < 2; ks++) {
            uint32_t af[2][4][4];
            uint32_t bf[2][4][2];
            const int choff = (ks << 1) + (lane >> 4);
#pragma unroll
            for (int mf = 0; mf < 4; mf++) {
                int row = wm + (mf << 4) + r15;
                uint32_t base = as0 + row * 128;
                int sw = row & 7;
                ldsm_x4(af[0][mf], base + ((choff ^ sw) << 4));
                ldsm_x4(af[1][mf], base + (((choff + 4) ^ sw) << 4));
            }
            const int krow = (ks << 4) + r15;
            const int swk = krow & 7;
#pragma unroll
            for (int nf = 0; nf < 4; nf++) {
                int chunk = (wn + (nf << 3)) >> 3;
                uint32_t ad = bs0 + krow * 256 + ((chunk ^ swk) << 4);
                ldsm_x2t(bf[0][nf], ad);
                ldsm_x2t(bf[1][nf], ad + 8192);
            }
#pragma unroll
            for (int mf = 0; mf < 4; mf++)
#pragma unroll
                for (int nf = 0; nf < 4; nf++) {
                    mma16816(acc[mf][nf], af[0][mf], bf[0][nf]);
                    mma16816(acc[mf][nf], af[0][mf], bf[1][nf]);
                    mma16816(acc[mf][nf], af[1][mf], bf[0][nf]);
                }
        }

        // store next tile into the other stage
        if (t + 1 < KT) {
            uint4 ah0, al0, ah1, al1, wh0, wl0, wh1, wl1;
            split8(ra[0], ra[1], ah0, al0);
            split8(ra[2], ra[3], ah1, al1);
            split8(rw[0], rw[1], wh0, wl0);
            split8(rw[2], rw[3], wh1, wl1);
            char* st = gsm + (cur ^ 1) * G_STAGE;
            *(uint4*)(st + aoff0) = ah0;
            *(uint4*)(st + aoff1) = ah1;
            *(uint4*)(st + aoff2) = al0;
            *(uint4*)(st + aoff3) = al1;
            *(uint4*)(st + G_BOFF + boff0) = wh0;
            *(uint4*)(st + G_BOFF + boff1) = wh1;
            *(uint4*)(st + G_BOFF + 8192 + boff0) = wl0;
            *(uint4*)(st + G_BOFF + 8192 + boff1) = wl1;
        }
        __syncthreads();
    }

    const int gr = lane >> 2, gc = (lane & 3) << 1;
#pragma unroll
    for (int mf = 0; mf < 4; mf++) {
        int r0 = bm + wm + (mf << 4) + gr;
#pragma unroll
        for (int nf = 0; nf < 4; nf++) {
            int col = bn + wn + (nf << 3) + gc;
            float2 bv = *(const float2*)(bias + col);
            float c00 = acc[mf][nf][0] + bv.x, c01 = acc[mf][nf][1] + bv.y;
            float c10 = acc[mf][nf][2] + bv.x, c11 = acc[mf][nf][3] + bv.y;
            if (mode == 0) {
                *(float2*)(Cf + (size_t)r0 * Nn + col) = make_float2(c00, c01);
                *(float2*)(Cf + (size_t)(r0 + 8) * Nn + col) = make_float2(c10, c11);
            } else {
                uint32_t h, l;
                split2(c00, c01, h, l);
                *(uint32_t*)(Ch + (size_t)r0 * Nn + col) = h;
                *(uint32_t*)(Cl + (size_t)r0 * Nn + col) = l;
                split2(c10, c11, h, l);
                *(uint32_t*)(Ch + (size_t)(r0 + 8) * Nn + col) = h;
                *(uint32_t*)(Cl + (size_t)(r0 + 8) * Nn + col) = l;
            }
        }
    }
}

// ---- round-3 energy: P = exp(mask ? QK^T/8 : -inf) fp32 unnorm, rowsums ----
__global__ __launch_bounds__(256) void attn_energy_tc(
    const __nv_bfloat16* __restrict__ qh, const __nv_bfloat16* __restrict__ ql,
    const __nv_bfloat16* __restrict__ kh, const __nv_bfloat16* __restrict__ kl,
    const int* __restrict__ mask, float* __restrict__ P)
{
    __shared__ __align__(16) __nv_bfloat16 Qh[64][64], Ql[64][64];
    __shared__ __align__(16) __nv_bfloat16 Kh[64][64], Kl[64][64];
    __shared__ float red[64][4];

    const int tid = threadIdx.x;
    const int warp = tid >> 5, lane = tid & 31;
    const int wm = (warp >> 2) << 5;
    const int wn = (warp & 3) << 4;
    const int bh = blockIdx.y;
    const int b = bh >> 4, h = bh & 15;
    const int q0 = blockIdx.x << 6;

    const uint32_t qh0 = smem_u32(&Qh[0][0]);
    const uint32_t ql0 = smem_u32(&Ql[0][0]);
    const uint32_t kh0 = smem_u32(&Kh[0][0]);
    const uint32_t kl0 = smem_u32(&Kl[0][0]);

    {
        int row = tid >> 2;
        int c0 = (tid & 3) << 1;
        const size_t base = ((size_t)(b * Ss + q0 + row)) * Dd + h * HD;
#pragma unroll
        for (int i = 0; i < 2; i++) {
            int c = c0 + i;
            int swc = (c ^ (row & 7)) << 3;
            *(uint4*)&Qh[row][swc] = *(const uint4*)(qh + base + (c << 3));
            *(uint4*)&Ql[row][swc] = *(const uint4*)(ql + base + (c << 3));
        }
    }

    float rs[2][2] = {{0.f, 0.f}, {0.f, 0.f}};
    const int gr = lane >> 2, gc = (lane & 3) << 1;
    const float sc = 0.125f;

    for (int kt = 0; kt < 16; kt++) {
        const int k0 = kt << 6;
        __syncthreads();
        {
            int row = tid >> 2;
            int c0 = (tid & 3) << 1;
            const size_t base = ((size_t)(b * Ss + k0 + row)) * Dd + h * HD;
#pragma unroll
            for (int i = 0; i < 2; i++) {
                int c = c0 + i;
                int swc = (c ^ (row & 7)) << 3;
                *(uint4*)&Kh[row][swc] = *(const uint4*)(kh + base + (c << 3));
                *(uint4*)&Kl[row][swc] = *(const uint4*)(kl + base + (c << 3));
            }
        }
        __syncthreads();

        float eacc[2][2][4];
#pragma unroll
        for (int i = 0; i < 2; i++)
#pragma unroll
            for (int j = 0; j < 2; j++)
#pragma unroll
                for (int r = 0; r < 4; r++) eacc[i][j][r] = 0.f;

#pragma unroll
        for (int ks = 0; ks < 4; ks++) {
            const int r15 = lane & 15;
            const int choff = (ks << 1) + (lane >> 4);
            uint32_t aH[2][4], aL[2][4];
#pragma unroll
            for (int mf = 0; mf < 2; mf++) {
                int row = wm + (mf << 4) + r15;
                int off = row * 128 + ((choff ^ (row & 7)) << 4);
                ldsm_x4(aH[mf], qh0 + off);
                ldsm_x4(aL[mf], ql0 + off);
            }
            int nrow = wn + ((lane >> 4) << 3) + (lane & 7);
            int kch = (ks << 1) + ((lane >> 3) & 1);
            int boff = nrow * 128 + ((kch ^ (nrow & 7)) << 4);
            uint32_t bH[4], bL[4];
            ldsm_x4(bH, kh0 + boff);
            ldsm_x4(bL, kl0 + boff);
#pragma unroll
            for (int mf = 0; mf < 2; mf++)
#pragma unroll
                for (int nf = 0; nf < 2; nf++) {
                    mma16816(eacc[mf][nf], aH[mf], bH + nf * 2);
                    mma16816(eacc[mf][nf], aH[mf], bL + nf * 2);
                    mma16816(eacc[mf][nf], aL[mf], bH + nf * 2);
                }
        }

#pragma unroll
        for (int mf = 0; mf < 2; mf++) {
            int row0 = q0 + wm + (mf << 4) + gr;
#pragma unroll
            for (int nf = 0; nf < 2; nf++) {
                int col = k0 + wn + (nf << 3) + gc;
                int m0 = mask[b * Ss + col];
                int m1 = mask[b * Ss + col + 1];
                float e0 = m0 ? __expf(eacc[mf][nf][0] * sc) : 0.f;
                float e1 = m1 ? __expf(eacc[mf][nf][1] * sc) : 0.f;
                float e2 = m0 ? __expf(eacc[mf][nf][2] * sc) : 0.f;
                float e3 = m1 ? __expf(eacc[mf][nf][3] * sc) : 0.f;
                rs[mf][0] += e0 + e1;
                rs[mf][1] += e2 + e3;
                *(float2*)(P + ((size_t)bh * Ss + row0) * Ss + col) = make_float2(e0, e1);
                *(float2*)(P + ((size_t)bh * Ss + row0 + 8) * Ss + col) = make_float2(e2, e3);
            }
        }
    }

#pragma unroll
    for (int mf = 0; mf < 2; mf++)
#pragma unroll
        for (int hf = 0; hf < 2; hf++) {
            float v = rs[mf][hf];
            v += __shfl_xor_sync(0xffffffff, v, 1);
            v += __shfl_xor_sync(0xffffffff, v, 2);
            if ((lane & 3) == 0)
                red[wm + (mf << 4) + gr + (hf << 3)][warp & 3] = v;
        }
    __syncthreads();
    if (tid < 64) {
        float s = red[tid][0] + red[tid][1] + red[tid][2] + red[tid][3];
        g_rowsum[(size_t)bh * Ss + q0 + tid] = s;
    }
}

// ---- round-3 PV: fused normalize + P write + X = P@V ----
__global__ __launch_bounds__(256) void attn_pv_tc(
    float* __restrict__ P,
    const __nv_bfloat16* __restrict__ vh, const __nv_bfloat16* __restrict__ vl,
    float* __restrict__ X)
{
    __shared__ __align__(16) __nv_bfloat16 Ph[64][64], Pl[64][64];
    __shared__ __align__(16) __nv_bfloat16 Vh[64][64], Vl[64][64];
    __shared__ float sinv[64];

    const int tid = threadIdx.x;
    const int warp = tid >> 5, lane = tid & 31;
    const int wm = (warp >> 2) << 5;
    const int wn = (warp & 3) << 4;
    const int bh = blockIdx.y;
    const int b = bh >> 4, h = bh & 15;
    const int q0 = blockIdx.x << 6;

    const uint32_t ph0 = smem_u32(&Ph[0][0]);
    const uint32_t pl0 = smem_u32(&Pl[0][0]);
    const uint32_t vh0 = smem_u32(&Vh[0][0]);
    const uint32_t vl0 = smem_u32(&Vl[0][0]);

    if (tid < 64)
        sinv[tid] = 1.0f / g_rowsum[(size_t)bh * Ss + q0 + tid];

    float acc[2][2][4];
#pragma unroll
    for (int i = 0; i < 2; i++)
#pragma unroll
        for (int j = 0; j < 2; j++)
#pragma unroll
            for (int r = 0; r < 4; r++) acc[i][j][r] = 0.f;

    const int prow = tid >> 2;
    const int pc0 = (tid & 3) << 4;
    const int pch0 = (tid & 3) << 1;

    for (int kt = 0; kt < 16; kt++) {
        const int k0 = kt << 6;
        __syncthreads();
        {
            int row = tid >> 2;
            int c0 = (tid & 3) << 1;
            const size_t base = ((size_t)(b * Ss + k0 + row)) * Dd + h * HD;
#pragma unroll
            for (int i = 0; i < 2; i++) {
                int c = c0 + i;
                int swc = (c ^ (row & 7)) << 3;
                *(uint4*)&Vh[row][swc] = *(const uint4*)(vh + base + (c << 3));
                *(uint4*)&Vl[row][swc] = *(const uint4*)(vl + base + (c << 3));
            }
        }
        {
            float* prow_g = P + ((size_t)bh * Ss + q0 + prow) * Ss + k0 + pc0;
            float inv = sinv[prow];
            float4 p0 = *(float4*)(prow_g);
            float4 p1 = *(float4*)(prow_g + 4);
            float4 p2 = *(float4*)(prow_g + 8);
            float4 p3 = *(float4*)(prow_g + 12);
            p0.x *= inv; p0.y *= inv; p0.z *= inv; p0.w *= inv;
            p1.x *= inv; p1.y *= inv; p1.z *= inv; p1.w *= inv;
            p2.x *= inv; p2.y *= inv; p2.z *= inv; p2.w *= inv;
            p3.x *= inv; p3.y *= inv; p3.z *= inv; p3.w *= inv;
            *(float4*)(prow_g) = p0;
            *(float4*)(prow_g + 4) = p1;
            *(float4*)(prow_g + 8) = p2;
            *(float4*)(prow_g + 12) = p3;
            uint4 h0, l0, h1, l1;
            split8(p0, p1, h0, l0);
            split8(p2, p3, h1, l1);
            int sw0 = ((pch0 | 0) ^ (prow & 7)) << 3;
            int sw1 = ((pch0 | 1) ^ (prow & 7)) << 3;
            *(uint4*)&Ph[prow][sw0] = h0;
            *(uint4*)&Ph[prow][sw1] = h1;
            *(uint4*)&Pl[prow][sw0] = l0;
            *(uint4*)&Pl[prow][sw1] = l1;
        }
        __syncthreads();

#pragma unroll
        for (int ks = 0; ks < 4; ks++) {
            const int r15 = lane & 15;
            const int choff = (ks << 1) + (lane >> 4);
            uint32_t aH[2][4], aL[2][4];
#pragma unroll
            for (int mf = 0; mf < 2; mf++) {
                int row = wm + (mf << 4) + r15;
                int off = row * 128 + ((choff ^ (row & 7)) << 4);
                ldsm_x4(aH[mf], ph0 + off);
                ldsm_x4(aL[mf], pl0 + off);
            }
            const int krow = (ks << 4) + r15;
            const int swk = krow & 7;
            uint32_t bH[2][2], bL[2][2];
#pragma unroll
            for (int nf = 0; nf < 2; nf++) {
                int chunk = (wn + (nf << 3)) >> 3;
                int boff = krow * 128 + ((chunk ^ swk) << 4);
                ldsm_x2t(bH[nf], vh0 + boff);
                ldsm_x2t(bL[nf], vl0 + boff);
            }
#pragma unroll
            for (int mf = 0; mf < 2; mf++)
#pragma unroll
                for (int nf = 0; nf < 2; nf++) {
                    mma16816(acc[mf][nf], aH[mf], bH[nf]);
                    mma16816(acc[mf][nf], aH[mf], bL[nf]);
                    mma16816(acc[mf][nf], aL[mf], bH[nf]);
                }
        }
    }
    const int gr = lane >> 2, gc = (lane & 3) << 1;
#pragma unroll
    for (int mf = 0; mf < 2; mf++) {
        int row0 = q0 + wm + (mf << 4) + gr;
#pragma unroll
        for (int nf = 0; nf < 2; nf++) {
            int col = h * HD + wn + (nf << 3) + gc;
            *(float2*)(X + ((size_t)(b * Ss + row0)) * Dd + col) =
                make_float2(acc[mf][nf][0], acc[mf][nf][1]);
            *(float2*)(X + ((size_t)(b * Ss + row0 + 8)) * Dd + col) =
                make_float2(acc[mf][nf][2], acc[mf][nf][3]);
        }
    }
}

// ---------------- launch ----------------
extern "C" void kernel_launch(void* const* d_in, const int* in_sizes, int n_in,
                              void* d_out, int out_size)
{
    const float* query = (const float*)d_in[0];
    const float* key   = (const float*)d_in[1];
    const float* value = (const float*)d_in[2];
    const int*   mask  = (const int*)d_in[3];
    const float* Wq = (const float*)d_in[4];  const float* bq = (const float*)d_in[5];
    const float* Wk = (const float*)d_in[6];  const float* bk = (const float*)d_in[7];
    const float* Wv = (const float*)d_in[8];  const float* bv = (const float*)d_in[9];
    const float* Wo = (const float*)d_in[10]; const float* bo = (const float*)d_in[11];

    float* out = (float*)d_out;
    const size_t BSD = (size_t)Bb * Ss * Dd;
    const size_t ATT = (size_t)BHt * Ss * Ss;

    void *pqh, *pql, *pkh, *pkl, *pvh, *pvl, *px;
    cudaGetSymbolAddress(&pqh, g_qh);
    cudaGetSymbolAddress(&pql, g_ql);
    cudaGetSymbolAddress(&pkh, g_kh);
    cudaGetSymbolAddress(&pkl, g_kl);
    cudaGetSymbolAddress(&pvh, g_vh);
    cudaGetSymbolAddress(&pvl, g_vl);
    cudaGetSymbolAddress(&px, g_x);
    __nv_bfloat16* qh = (__nv_bfloat16*)pqh;
    __nv_bfloat16* ql = (__nv_bfloat16*)pql;
    __nv_bfloat16* kh = (__nv_bfloat16*)pkh;
    __nv_bfloat16* kl = (__nv_bfloat16*)pkl;
    __nv_bfloat16* vh = (__nv_bfloat16*)pvh;
    __nv_bfloat16* vl = (__nv_bfloat16*)pvl;
    float* x = (float*)px;

    float* P;
    if ((size_t)out_size >= BSD + ATT) {
        P = out + BSD;
    } else {
        void* pp;
        cudaGetSymbolAddress(&pp, g_p_fallback);
        P = (float*)pp;
    }

    cudaFuncSetAttribute(gemm_f32_tc,
                         cudaFuncAttributeMaxDynamicSharedMemorySize, G_SMEM);

    dim3 gemm_grid(Dd / 128, Mrows / 128);  // (8, 32)

    gemm_f32_tc<<<gemm_grid, 256, G_SMEM>>>(query, Wq, bq, nullptr, qh, ql, 1, Mrows, Dd, Dd);
    gemm_f32_tc<<<gemm_grid, 256, G_SMEM>>>(key,   Wk, bk, nullptr, kh, kl, 1, Mrows, Dd, Dd);
    gemm_f32_tc<<<gemm_grid, 256, G_SMEM>>>(value, Wv, bv, nullptr, vh, vl, 1, Mrows, Dd, Dd);

    attn_energy_tc<<<dim3(Ss / 64, BHt), 256>>>(qh, ql, kh, kl, mask, P);
    attn_pv_tc<<<dim3(Ss / 64, BHt), 256>>>(P, vh, vl, x);

    gemm_f32_tc<<<gemm_grid, 256, G_SMEM>>>(x, Wo, bo, out, nullptr, nullptr, 0, Mrows, Dd, Dd);
}